// round 9
// baseline (speedup 1.0000x reference)
#include <cuda_runtime.h>
#include <cuda_bf16.h>
#include <cuda_fp16.h>
#include <cuda_fp8.h>
#include <cstdint>

// Problem constants (fixed shape: path_fea [131072, 64, 1, 1, 2] fp32)
#define GNUM 8192        // groups = B / 16
#define PNUM 16          // samples per group
#define DNUM 128         // feature dim
#define NTILE 64         // GNUM / 128
#define NTILES_TRI 2080  // 64*65/2 triangular 128x128 tiles
#define GRID_B 296       // persistent CTAs (148 SMs * 2, guaranteed resident)
#define TROW 144         // smem tile row stride in bytes (128 fp8 + 16 pad)
#define TILEB (128 * TROW)   // 18432 B per fp8 tile

// -------- device scratch (no allocs allowed) --------
__device__ uint8_t g_centerF8[GNUM * DNUM];   // e4m3 centers (k-major, 128B/row)
__device__ float g_sq[GNUM];                  // fp32 ||c||^2
__device__ float g_intra_part[GRID_B];
__device__ float g_inter_part[GRID_B];
__device__ unsigned int g_done = 0;           // self-resetting
__device__ unsigned int g_sync = 0;           // self-resetting grid barrier

// ===================== helpers =====================
__device__ __forceinline__ uint32_t smem_u32(const void* p) {
    uint32_t a;
    asm("{ .reg .u64 t; cvta.to.shared.u64 t, %1; cvt.u32.u64 %0, t; }"
        : "=r"(a) : "l"(p));
    return a;
}
__device__ __forceinline__ void cp16(uint32_t dst, const void* src) {
    asm volatile("cp.async.cg.shared.global [%0], [%1], 16;"
                 :: "r"(dst), "l"(src) : "memory");
}
__device__ __forceinline__ void cp_commit() {
    asm volatile("cp.async.commit_group;" ::: "memory");
}
__device__ __forceinline__ void cp_wait0() {
    asm volatile("cp.async.wait_group 0;" ::: "memory");
}
__device__ __forceinline__ void cp_wait1() {
    asm volatile("cp.async.wait_group 1;" ::: "memory");
}
__device__ __forceinline__ void ldm_x4(uint32_t (&r)[4], const void* p) {
    uint32_t addr = smem_u32(p);
    asm volatile("ldmatrix.sync.aligned.m8n8.x4.shared.b16 {%0,%1,%2,%3}, [%4];"
        : "=r"(r[0]), "=r"(r[1]), "=r"(r[2]), "=r"(r[3]) : "r"(addr));
}
// FP8 e4m3 MMA with f16 accumulators
__device__ __forceinline__ void mma_fp8_h(uint32_t (&d)[2], const uint32_t (&a)[4],
                                          uint32_t b0, uint32_t b1) {
    asm volatile(
        "mma.sync.aligned.m16n8k32.row.col.f16.e4m3.e4m3.f16 "
        "{%0,%1}, {%2,%3,%4,%5}, {%6,%7}, {%0,%1};"
        : "+r"(d[0]), "+r"(d[1])
        : "r"(a[0]), "r"(a[1]), "r"(a[2]), "r"(a[3]), "r"(b0), "r"(b1));
}

// ============================================================
// Single fused persistent kernel:
//   Phase 1: centers + ||c||^2 + intra hinge (cp.async pipelined)
//   grid-wide barrier (all GRID_B CTAs resident by construction)
//   Phase 2: FP8 QMMA SYRK, A-fragments register-resident per row-run
//   finalize: last CTA reduces partials, resets counters
// ============================================================
__global__ void __launch_bounds__(256, 2) lda_fused_kernel(const float* __restrict__ fea,
                                                           float* __restrict__ out) {
    extern __shared__ uint8_t sm[];
    __shared__ float sc[DNUM];
    __shared__ float s_red[8], s_red2[8];
    __shared__ float s_gmin;
    __shared__ unsigned s_last;

    const int tid = threadIdx.x;
    const int wid = tid >> 5, lane = tid & 31;
    const int bid = blockIdx.x;

    // ================= Phase 1: centers / intra =================
    float intra_acc = 0.0f;
    {
        const int g0 = (bid * GNUM) / GRID_B;
        const int g1 = ((bid + 1) * GNUM) / GRID_B;
        float* pb[3] = { (float*)sm, (float*)(sm + 8192), (float*)(sm + 16384) };

        // issue one group's 8KB as one commit group (2 x 16B per thread)
        auto issue = [&](int g) {
            const char* src = (const char*)fea + (size_t)g * 8192;
            char* dst = (char*)pb[g % 3];
            cp16(smem_u32(dst + tid * 16), src + tid * 16);
            cp16(smem_u32(dst + 4096 + tid * 16), src + 4096 + tid * 16);
            cp_commit();
        };
        issue(g0);
        if (g0 + 1 < g1) issue(g0 + 1);

        for (int g = g0; g < g1; g++) {
            if (g + 1 < g1) cp_wait1(); else cp_wait0();
            __syncthreads();           // buffer (g) ready; all warps done with g-1
            if (g + 2 < g1) issue(g + 2);

            const float* sf = pb[g % 3];
            // center: threads 0..127 own one dim each
            if (tid < DNUM) {
                float c = 0.0f;
                #pragma unroll
                for (int s = 0; s < PNUM; s++) c += sf[s * DNUM + tid];
                c *= (1.0f / PNUM);
                sc[tid] = c;
                g_centerF8[(size_t)g * DNUM + tid] =
                    (uint8_t)__nv_cvt_float_to_fp8(c, __NV_SATFINITE, __NV_E4M3);
                float cs = c * c;
                #pragma unroll
                for (int o = 16; o > 0; o >>= 1)
                    cs += __shfl_down_sync(0xffffffffu, cs, o);
                if (lane == 0) s_red[wid] = cs;
            }
            __syncthreads();
            if (tid == 0) g_sq[g] = s_red[0] + s_red[1] + s_red[2] + s_red[3];

            // intra: warp w handles samples w and w+8
            #pragma unroll
            for (int ss = 0; ss < 2; ss++) {
                const int s = wid + ss * 8;
                float a = 0.0f;
                #pragma unroll
                for (int q = 0; q < 4; q++) {
                    int d = lane + 32 * q;
                    float df = sf[s * DNUM + d] - sc[d];
                    a += df * df;
                }
                #pragma unroll
                for (int o = 16; o > 0; o >>= 1)
                    a += __shfl_down_sync(0xffffffffu, a, o);
                if (lane == 0) {
                    float dd = fmaxf(sqrtf(a) - 0.1f, 0.0f);
                    intra_acc += dd * dd;
                }
            }
        }
    }

    // ================= grid-wide barrier =================
    __threadfence();
    __syncthreads();
    if (tid == 0) {
        atomicAdd(&g_sync, 1u);
        volatile unsigned int* vs = &g_sync;
        while (*vs < GRID_B) __nanosleep(64);
    }
    __syncthreads();
    __threadfence();   // acquire: all CTAs' phase-1 writes now visible

    // ================= Phase 2: FP8 SYRK =================
    uint8_t* bufA[2] = { sm, sm + TILEB };
    uint8_t* bufB[2] = { sm + 2 * TILEB, sm + 3 * TILEB };

    const int t0 = (int)(((long long)bid * NTILES_TRI) / GRID_B);
    const int t1 = (int)(((long long)(bid + 1) * NTILES_TRI) / GRID_B);
    int ti = 0, rowoff = 0;
    while (t0 >= rowoff + (NTILE - ti)) { rowoff += NTILE - ti; ti++; }
    int tj = ti + (t0 - rowoff);

    const uint8_t* gcb = g_centerF8;
    auto load_tile = [&](uint8_t* dst, int gg0) {
        #pragma unroll
        for (int i = 0; i < 4; i++) {
            int u = tid + 256 * i;
            int r = u >> 3, c16 = (u & 7) * 16;
            cp16(smem_u32(dst + r * TROW + c16),
                 gcb + (size_t)(gg0 + r) * 128 + c16);
        }
    };

    // prologue tile loads (overlap with gmin scan)
    load_tile(bufA[0], ti * 128);
    load_tile(bufB[0], tj * 128);
    cp_commit();

    // global min of ||c||^2 for the no-hinge screen
    {
        float m = 3.4e38f;
        for (int i = tid; i < GNUM; i += 256) m = fminf(m, g_sq[i]);
        #pragma unroll
        for (int o = 16; o > 0; o >>= 1)
            m = fminf(m, __shfl_xor_sync(0xffffffffu, m, o));
        if (lane == 0) s_red[wid] = m;
        __syncthreads();
        if (tid == 0) {
            float mm = s_red[0];
            #pragma unroll
            for (int w = 1; w < 8; w++) mm = fminf(mm, s_red[w]);
            s_gmin = mm;
        }
        __syncthreads();
    }
    const float screen = s_gmin - 0.5f;

    const int wm = wid & 1;
    const int wn = wid >> 1;
    const int lrow = lane & 15;
    const int lcolB = ((lane >> 4) << 3) * 2;
    const int r_l = lane >> 2;
    const int c_l = 2 * (lane & 3);

    uint32_t a_frag[4][4][4];   // [mt][ks][reg] — register-resident A tile
    int reg_ti = -1;
    int aCur = 0, bCur = 0;
    float lsum = 0.0f;

    for (int t = t0; t < t1; t++) {
        const int i0 = ti * 128, j0 = tj * 128;
        cp_wait0();
        __syncthreads();

        if (ti != reg_ti) {   // new row-run: refresh A fragments (16 ldmatrix)
            #pragma unroll
            for (int mt = 0; mt < 4; mt++)
                #pragma unroll
                for (int ks = 0; ks < 4; ks++)
                    ldm_x4(a_frag[mt][ks],
                           bufA[aCur] + (64 * wm + 16 * mt + lrow) * TROW + ks * 32 + lcolB);
            reg_ti = ti;
        }

        int nti = ti, ntj = tj + 1;
        if (ntj == NTILE) { nti = ti + 1; ntj = nti; }
        const bool havenext = (t + 1 < t1);
        const bool newrow = (nti != ti);
        if (havenext) {
            if (newrow) load_tile(bufA[aCur ^ 1], nti * 128);
            load_tile(bufB[bCur ^ 1], ntj * 128);
            cp_commit();
        }

        // ---- compute: 4 k-steps, B ldmatrix only (A in regs) ----
        const uint8_t* sB = bufB[bCur];
        uint32_t acc[4][4][2];
        #pragma unroll
        for (int mt = 0; mt < 4; mt++)
            #pragma unroll
            for (int nt = 0; nt < 4; nt++) { acc[mt][nt][0] = 0u; acc[mt][nt][1] = 0u; }

        #pragma unroll
        for (int ks = 0; ks < 4; ks++) {
            const int kb = ks * 32;
            uint32_t b0r[4], b1r[4];
            ldm_x4(b0r, sB + (32 * wn + lrow) * TROW + kb + lcolB);
            ldm_x4(b1r, sB + (32 * wn + 16 + lrow) * TROW + kb + lcolB);
            #pragma unroll
            for (int mt = 0; mt < 4; mt++) {
                mma_fp8_h(acc[mt][0], a_frag[mt][ks], b0r[0], b0r[2]);
                mma_fp8_h(acc[mt][1], a_frag[mt][ks], b0r[1], b0r[3]);
                mma_fp8_h(acc[mt][2], a_frag[mt][ks], b1r[0], b1r[2]);
                mma_fp8_h(acc[mt][3], a_frag[mt][ks], b1r[1], b1r[3]);
            }
        }

        // ---- epilogue: packed-max screen, exact path only if needed ----
        const bool diag = (ti == tj);
        __half2 m2 = __float2half2_rn(-60000.0f);
        #pragma unroll
        for (int mt = 0; mt < 4; mt++)
            #pragma unroll
            for (int nt = 0; nt < 4; nt++) {
                m2 = __hmax2(m2, *(const __half2*)&acc[mt][nt][0]);
                m2 = __hmax2(m2, *(const __half2*)&acc[mt][nt][1]);
            }
        float maxg = fmaxf(__low2float(m2), __high2float(m2));

        if (diag || maxg > screen) {
            #pragma unroll
            for (int mt = 0; mt < 4; mt++) {
                const int li0 = 64 * wm + 16 * mt + r_l;
                const float qa0 = __ldg(&g_sq[i0 + li0]);
                const float qa1 = __ldg(&g_sq[i0 + li0 + 8]);
                #pragma unroll
                for (int nt = 0; nt < 4; nt++) {
                    const int lj0 = 32 * wn + 8 * nt + c_l;
                    const float qb0 = __ldg(&g_sq[j0 + lj0]);
                    const float qb1 = __ldg(&g_sq[j0 + lj0 + 1]);
                    float2 v0 = __half22float2(*(const __half2*)&acc[mt][nt][0]);
                    float2 v1 = __half22float2(*(const __half2*)&acc[mt][nt][1]);
                    const float gv[4]  = { v0.x, v0.y, v1.x, v1.y };
                    const float qav[4] = { qa0, qa0, qa1, qa1 };
                    const float qbv[4] = { qb0, qb1, qb0, qb1 };
                    const int liv[4] = { li0, li0, li0 + 8, li0 + 8 };
                    const int ljv[4] = { lj0, lj0 + 1, lj0, lj0 + 1 };
                    #pragma unroll
                    for (int e = 0; e < 4; e++) {
                        bool ok = !diag || (liv[e] < ljv[e]);
                        float d2 = qav[e] + qbv[e] - 2.0f * gv[e];
                        if (ok && d2 < 1.0f) {
                            float d = sqrtf(fmaxf(d2, 0.0f));
                            float h = 1.0f - d;
                            lsum += h * h;
                        }
                    }
                }
            }
        }

        if (havenext) {
            if (newrow) aCur ^= 1;
            bCur ^= 1;
            ti = nti; tj = ntj;
        }
    }

    // ================= per-CTA reduction + finalize =================
    #pragma unroll
    for (int o = 16; o > 0; o >>= 1) {
        lsum      += __shfl_down_sync(0xffffffffu, lsum, o);
        intra_acc += __shfl_down_sync(0xffffffffu, intra_acc, o);
    }
    __syncthreads();
    if (lane == 0) { s_red[wid] = lsum; s_red2[wid] = intra_acc; }
    __syncthreads();
    if (tid == 0) {
        float a = 0.0f, b = 0.0f;
        #pragma unroll
        for (int w = 0; w < 8; w++) { a += s_red[w]; b += s_red2[w]; }
        g_inter_part[bid] = a;
        g_intra_part[bid] = b;
    }

    __threadfence();
    __syncthreads();
    if (tid == 0) {
        unsigned v = atomicAdd(&g_done, 1u);
        s_last = (v == GRID_B - 1) ? 1u : 0u;
    }
    __syncthreads();
    if (s_last) {
        __threadfence();
        float a = 0.0f, b = 0.0f;
        for (int i = tid; i < GRID_B; i += 256) { a += g_inter_part[i]; b += g_intra_part[i]; }
        #pragma unroll
        for (int o = 16; o > 0; o >>= 1) {
            a += __shfl_down_sync(0xffffffffu, a, o);
            b += __shfl_down_sync(0xffffffffu, b, o);
        }
        __shared__ float fa[8], fb[8];
        if (lane == 0) { fa[wid] = a; fb[wid] = b; }
        __syncthreads();
        if (tid == 0) {
            float A = 0.0f, B = 0.0f;
            #pragma unroll
            for (int w = 0; w < 8; w++) { A += fa[w]; B += fb[w]; }
            out[0] = A / 33550336.0f;              // G*(G-1)/2
            out[1] = B / (float)(GNUM * PNUM);
            g_done = 0;                            // reset for next replay
            g_sync = 0;
        }
    }
}

extern "C" void kernel_launch(void* const* d_in, const int* in_sizes, int n_in,
                              void* d_out, int out_size) {
    const float* fea = (const float*)d_in[0];
    float* out = (float*)d_out;

    const int smem_bytes = 4 * TILEB;   // 73728
    cudaFuncSetAttribute(lda_fused_kernel,
                         cudaFuncAttributeMaxDynamicSharedMemorySize, smem_bytes);
    lda_fused_kernel<<<GRID_B, 256, smem_bytes>>>(fea, out);
}

// round 10
// speedup vs baseline: 1.1110x; 1.1110x over previous
#include <cuda_runtime.h>
#include <cuda_bf16.h>
#include <cuda_fp16.h>
#include <cuda_fp8.h>
#include <cstdint>

// Problem constants (fixed shape: path_fea [131072, 64, 1, 1, 2] fp32)
#define GNUM 8192        // groups = B / 16
#define PNUM 16          // samples per group
#define DNUM 128         // feature dim
#define NTILE 64         // GNUM / 128
#define NTILES_TRI 2080  // 64*65/2 triangular 128x128 tiles
#define GRID_B 296       // persistent CTAs (148 SMs * 2, exact residency)
#define TROW 144         // smem tile row stride in bytes (128 fp8 + 16 pad)
#define TILEB (128 * TROW)

// -------- device scratch (no allocs allowed) --------
__device__ uint8_t g_centerF8[GNUM * DNUM];   // e4m3 centers (k-major, 128B/row)
__device__ float g_sq[GNUM];                  // fp32 ||c||^2
__device__ float g_intra_part[GNUM];
__device__ float g_inter_part[GRID_B];
__device__ unsigned int g_done = 0;           // self-resetting

// ===================== helpers =====================
__device__ __forceinline__ uint32_t smem_u32(const void* p) {
    uint32_t a;
    asm("{ .reg .u64 t; cvta.to.shared.u64 t, %1; cvt.u32.u64 %0, t; }"
        : "=r"(a) : "l"(p));
    return a;
}
__device__ __forceinline__ void cp16(uint32_t dst, const void* src) {
    asm volatile("cp.async.cg.shared.global [%0], [%1], 16;"
                 :: "r"(dst), "l"(src) : "memory");
}
__device__ __forceinline__ void cp_commit() {
    asm volatile("cp.async.commit_group;" ::: "memory");
}
__device__ __forceinline__ void cp_wait0() {
    asm volatile("cp.async.wait_group 0;" ::: "memory");
}
__device__ __forceinline__ void ldm_x4(uint32_t (&r)[4], const void* p) {
    uint32_t addr = smem_u32(p);
    asm volatile("ldmatrix.sync.aligned.m8n8.x4.shared.b16 {%0,%1,%2,%3}, [%4];"
        : "=r"(r[0]), "=r"(r[1]), "=r"(r[2]), "=r"(r[3]) : "r"(addr));
}
// FP8 e4m3 MMA with f16 accumulators
__device__ __forceinline__ void mma_fp8_h(uint32_t (&d)[2], const uint32_t (&a)[4],
                                          uint32_t b0, uint32_t b1) {
    asm volatile(
        "mma.sync.aligned.m16n8k32.row.col.f16.e4m3.e4m3.f16 "
        "{%0,%1}, {%2,%3,%4,%5}, {%6,%7}, {%0,%1};"
        : "+r"(d[0]), "+r"(d[1])
        : "r"(a[0]), "r"(a[1]), "r"(a[2]), "r"(a[3]), "r"(b0), "r"(b1));
}

// ============================================================
// Kernel A: per-group center + ||c||^2 + intra hinge (memory-bound,
// wide grid: 8192 CTAs to saturate HBM)
// ============================================================
__global__ void __launch_bounds__(512) center_intra_kernel(const float* __restrict__ fea) {
    __shared__ float sf[PNUM * DNUM];
    __shared__ float sc[DNUM];
    __shared__ float s_red[4];
    __shared__ float s_h[PNUM];

    const int g = blockIdx.x;
    const int tid = threadIdx.x;

    const float4* base4 = (const float4*)(fea + (size_t)g * (PNUM * DNUM));
    ((float4*)sf)[tid] = base4[tid];
    __syncthreads();

    float c = 0.0f;
    if (tid < DNUM) {
        #pragma unroll
        for (int s = 0; s < PNUM; s++) c += sf[s * DNUM + tid];
        c *= (1.0f / PNUM);
        sc[tid] = c;
        g_centerF8[(size_t)g * DNUM + tid] =
            (uint8_t)__nv_cvt_float_to_fp8(c, __NV_SATFINITE, __NV_E4M3);
    }
    float cs = (tid < DNUM) ? c * c : 0.0f;
    #pragma unroll
    for (int o = 16; o > 0; o >>= 1) cs += __shfl_down_sync(0xffffffffu, cs, o);
    if (tid < DNUM && (tid & 31) == 0) s_red[tid >> 5] = cs;
    __syncthreads();
    if (tid == 0) g_sq[g] = s_red[0] + s_red[1] + s_red[2] + s_red[3];

    const int w = tid >> 5, l = tid & 31;
    float acc = 0.0f;
    #pragma unroll
    for (int q = 0; q < 4; q++) {
        int dd = l + 32 * q;
        float df = sf[w * DNUM + dd] - sc[dd];
        acc += df * df;
    }
    #pragma unroll
    for (int o = 16; o > 0; o >>= 1) acc += __shfl_down_sync(0xffffffffu, acc, o);
    if (l == 0) {
        float d = fmaxf(sqrtf(acc) - 0.1f, 0.0f);
        s_h[w] = d * d;
    }
    __syncthreads();
    if (tid == 0) {
        float t = 0.0f;
        #pragma unroll
        for (int s = 0; s < PNUM; s++) t += s_h[s];
        g_intra_part[g] = t;
    }
}

// ============================================================
// Kernel B: persistent FP8 QMMA SYRK (128x128 tiles, f16 accum),
// A-fragments register-resident per row-run, double-buffered B,
// max-screened hinge epilogue, fused finalize (last CTA).
// ============================================================
__global__ void __launch_bounds__(256, 2) gram_finalize_kernel(float* __restrict__ out) {
    extern __shared__ uint8_t sm[];
    uint8_t* bufA[2] = { sm, sm + TILEB };
    uint8_t* bufB[2] = { sm + 2 * TILEB, sm + 3 * TILEB };

    __shared__ float s_red[8];
    __shared__ float s_gmin;
    __shared__ unsigned s_last;

    const int tid = threadIdx.x;
    const int wid = tid >> 5, lane = tid & 31;

    const int t0 = (int)(((long long)blockIdx.x * NTILES_TRI) / gridDim.x);
    const int t1 = (int)(((long long)(blockIdx.x + 1) * NTILES_TRI) / gridDim.x);

    int ti = 0, rowoff = 0;
    while (t0 >= rowoff + (NTILE - ti)) { rowoff += NTILE - ti; ti++; }
    int tj = ti + (t0 - rowoff);

    const uint8_t* gcb = g_centerF8;
    auto load_tile = [&](uint8_t* dst, int g0) {
        #pragma unroll
        for (int i = 0; i < 4; i++) {
            int u = tid + 256 * i;
            int r = u >> 3, c16 = (u & 7) * 16;
            cp16(smem_u32(dst + r * TROW + c16),
                 gcb + (size_t)(g0 + r) * 128 + c16);
        }
    };

    // prologue loads (overlap with gmin scan)
    load_tile(bufA[0], ti * 128);
    load_tile(bufB[0], tj * 128);
    cp_commit();

    // global min of ||c||^2 for the no-hinge screen
    {
        float m = 3.4e38f;
        for (int i = tid; i < GNUM; i += 256) m = fminf(m, g_sq[i]);
        #pragma unroll
        for (int o = 16; o > 0; o >>= 1)
            m = fminf(m, __shfl_xor_sync(0xffffffffu, m, o));
        if (lane == 0) s_red[wid] = m;
        __syncthreads();
        if (tid == 0) {
            float mm = s_red[0];
            #pragma unroll
            for (int w = 1; w < 8; w++) mm = fminf(mm, s_red[w]);
            s_gmin = mm;
        }
        __syncthreads();
    }
    const float screen = s_gmin - 0.5f;

    const int wm = wid & 1;
    const int wn = wid >> 1;
    const int lrow = lane & 15;
    const int lcolB = ((lane >> 4) << 3) * 2;
    const int r_l = lane >> 2;
    const int c_l = 2 * (lane & 3);

    uint32_t a_frag[4][4][4];   // [mt][ks][reg] — register-resident A tile
    int reg_ti = -1;
    int aCur = 0, bCur = 0;
    float lsum = 0.0f;

    for (int t = t0; t < t1; t++) {
        const int i0 = ti * 128, j0 = tj * 128;
        cp_wait0();
        __syncthreads();

        if (ti != reg_ti) {   // new row-run: refresh A fragments (16 ldmatrix)
            #pragma unroll
            for (int mt = 0; mt < 4; mt++)
                #pragma unroll
                for (int ks = 0; ks < 4; ks++)
                    ldm_x4(a_frag[mt][ks],
                           bufA[aCur] + (64 * wm + 16 * mt + lrow) * TROW + ks * 32 + lcolB);
            reg_ti = ti;
        }

        int nti = ti, ntj = tj + 1;
        if (ntj == NTILE) { nti = ti + 1; ntj = nti; }
        const bool havenext = (t + 1 < t1);
        const bool newrow = (nti != ti);
        if (havenext) {
            if (newrow) load_tile(bufA[aCur ^ 1], nti * 128);
            load_tile(bufB[bCur ^ 1], ntj * 128);
            cp_commit();
        }

        // ---- compute: 4 k-steps, B ldmatrix only (A in regs) ----
        const uint8_t* sB = bufB[bCur];
        uint32_t acc[4][4][2];
        #pragma unroll
        for (int mt = 0; mt < 4; mt++)
            #pragma unroll
            for (int nt = 0; nt < 4; nt++) { acc[mt][nt][0] = 0u; acc[mt][nt][1] = 0u; }

        #pragma unroll
        for (int ks = 0; ks < 4; ks++) {
            const int kb = ks * 32;
            uint32_t b0r[4], b1r[4];
            ldm_x4(b0r, sB + (32 * wn + lrow) * TROW + kb + lcolB);
            ldm_x4(b1r, sB + (32 * wn + 16 + lrow) * TROW + kb + lcolB);
            #pragma unroll
            for (int mt = 0; mt < 4; mt++) {
                mma_fp8_h(acc[mt][0], a_frag[mt][ks], b0r[0], b0r[2]);
                mma_fp8_h(acc[mt][1], a_frag[mt][ks], b0r[1], b0r[3]);
                mma_fp8_h(acc[mt][2], a_frag[mt][ks], b1r[0], b1r[2]);
                mma_fp8_h(acc[mt][3], a_frag[mt][ks], b1r[1], b1r[3]);
            }
        }

        // ---- epilogue: packed-max screen, exact path only if needed ----
        const bool diag = (ti == tj);
        __half2 m2 = __float2half2_rn(-60000.0f);
        #pragma unroll
        for (int mt = 0; mt < 4; mt++)
            #pragma unroll
            for (int nt = 0; nt < 4; nt++) {
                m2 = __hmax2(m2, *(const __half2*)&acc[mt][nt][0]);
                m2 = __hmax2(m2, *(const __half2*)&acc[mt][nt][1]);
            }
        float maxg = fmaxf(__low2float(m2), __high2float(m2));

        if (diag || maxg > screen) {
            #pragma unroll
            for (int mt = 0; mt < 4; mt++) {
                const int li0 = 64 * wm + 16 * mt + r_l;
                const float qa0 = __ldg(&g_sq[i0 + li0]);
                const float qa1 = __ldg(&g_sq[i0 + li0 + 8]);
                #pragma unroll
                for (int nt = 0; nt < 4; nt++) {
                    const int lj0 = 32 * wn + 8 * nt + c_l;
                    const float qb0 = __ldg(&g_sq[j0 + lj0]);
                    const float qb1 = __ldg(&g_sq[j0 + lj0 + 1]);
                    float2 v0 = __half22float2(*(const __half2*)&acc[mt][nt][0]);
                    float2 v1 = __half22float2(*(const __half2*)&acc[mt][nt][1]);
                    const float gv[4]  = { v0.x, v0.y, v1.x, v1.y };
                    const float qav[4] = { qa0, qa0, qa1, qa1 };
                    const float qbv[4] = { qb0, qb1, qb0, qb1 };
                    const int liv[4] = { li0, li0, li0 + 8, li0 + 8 };
                    const int ljv[4] = { lj0, lj0 + 1, lj0, lj0 + 1 };
                    #pragma unroll
                    for (int e = 0; e < 4; e++) {
                        bool ok = !diag || (liv[e] < ljv[e]);
                        float d2 = qav[e] + qbv[e] - 2.0f * gv[e];
                        if (ok && d2 < 1.0f) {
                            float d = sqrtf(fmaxf(d2, 0.0f));
                            float h = 1.0f - d;
                            lsum += h * h;
                        }
                    }
                }
            }
        }

        if (havenext) {
            if (newrow) aCur ^= 1;
            bCur ^= 1;
            ti = nti; tj = ntj;
        }
    }

    // per-CTA inter reduction
    #pragma unroll
    for (int o = 16; o > 0; o >>= 1) lsum += __shfl_down_sync(0xffffffffu, lsum, o);
    __syncthreads();
    if (lane == 0) s_red[wid] = lsum;
    __syncthreads();
    if (tid == 0) {
        float tsum = 0.0f;
        #pragma unroll
        for (int w = 0; w < 8; w++) tsum += s_red[w];
        g_inter_part[blockIdx.x] = tsum;
    }

    // last-CTA-done finalize
    __threadfence();
    __syncthreads();
    if (tid == 0) {
        unsigned v = atomicAdd(&g_done, 1u);
        s_last = (v == gridDim.x - 1) ? 1u : 0u;
    }
    __syncthreads();
    if (s_last) {
        __threadfence();
        float a = 0.0f, b = 0.0f;
        for (int i = tid; i < GRID_B; i += 256) a += g_inter_part[i];
        for (int i = tid; i < GNUM; i += 256) b += g_intra_part[i];
        #pragma unroll
        for (int o = 16; o > 0; o >>= 1) {
            a += __shfl_down_sync(0xffffffffu, a, o);
            b += __shfl_down_sync(0xffffffffu, b, o);
        }
        __shared__ float fa[8], fb[8];
        if (lane == 0) { fa[wid] = a; fb[wid] = b; }
        __syncthreads();
        if (tid == 0) {
            float A = 0.0f, B = 0.0f;
            #pragma unroll
            for (int w = 0; w < 8; w++) { A += fa[w]; B += fb[w]; }
            out[0] = A / 33550336.0f;              // G*(G-1)/2
            out[1] = B / (float)(GNUM * PNUM);
            g_done = 0;                            // reset for next replay
        }
    }
}

extern "C" void kernel_launch(void* const* d_in, const int* in_sizes, int n_in,
                              void* d_out, int out_size) {
    const float* fea = (const float*)d_in[0];
    float* out = (float*)d_out;

    center_intra_kernel<<<GNUM, 512>>>(fea);

    const int smem_bytes = 4 * TILEB;   // 73728
    cudaFuncSetAttribute(gram_finalize_kernel,
                         cudaFuncAttributeMaxDynamicSharedMemorySize, smem_bytes);
    gram_finalize_kernel<<<GRID_B, 256, smem_bytes>>>(out);
}